// round 1
// baseline (speedup 1.0000x reference)
#include <cuda_runtime.h>
#include <stdint.h>

// TrafficGCN: 2-layer GCN, N=100000 nodes, E=3200000 edges, HIDDEN=16.
// out = GCNConv(relu(GCNConv(x; W1,b1)); W2,b2), symmetric norm, self-loops.
//
// Inputs (metadata order):
//   d_in[0] = x          float32 [N,3]
//   d_in[1] = edge_index int32   [2,E]  (row0 = src, row1 = dst)
//   d_in[2] = W1         float32 [3,16]
//   d_in[3] = b1         float32 [16]
//   d_in[4] = W2         float32 [16,1]
//   d_in[5] = b2         float32 [1]
// Output: float32 [N]

#define MAXN 100608   // >= 100000, padded
#define HID 16

// Scratch (static device globals — allocation-free rule)
__device__ int    g_degcnt[MAXN];
__device__ float  g_isd[MAXN];
__device__ float4 g_xw[MAXN * 4];   // x @ W1, 16 floats per node as 4x float4
__device__ float4 g_h [MAXN * 4];   // aggregated hidden (pre-bias/relu)
__device__ float  g_g [MAXN];       // relu(h+b1) @ W2 per node

// ---------------------------------------------------------------------------
__global__ void k_zero_deg(int n) {
    int i = blockIdx.x * blockDim.x + threadIdx.x;
    if (i < n) g_degcnt[i] = 0;
}

__global__ void k_count(const int* __restrict__ dst, int E) {
    int e = blockIdx.x * blockDim.x + threadIdx.x;
    if (e < E) atomicAdd(&g_degcnt[dst[e]], 1);
}

// Per-node: isd = rsqrt(deg+1); xw = x@W1; h seeded with self-loop isd^2 * xw
__global__ void k_node1(const float* __restrict__ x,
                        const float* __restrict__ W1, int n) {
    int i = blockIdx.x * blockDim.x + threadIdx.x;
    if (i >= n) return;
    float deg = (float)(g_degcnt[i] + 1);   // +1 self-loop; always > 0
    float isd = rsqrtf(deg);
    g_isd[i] = isd;
    float sl = isd * isd;                   // self-loop norm

    float x0 = x[3 * i + 0];
    float x1 = x[3 * i + 1];
    float x2 = x[3 * i + 2];

    float w[HID];
#pragma unroll
    for (int c = 0; c < HID; c++) {
        w[c] = x0 * __ldg(&W1[c]) + x1 * __ldg(&W1[HID + c]) + x2 * __ldg(&W1[2 * HID + c]);
    }
#pragma unroll
    for (int q = 0; q < 4; q++) {
        float4 v = make_float4(w[4 * q + 0], w[4 * q + 1], w[4 * q + 2], w[4 * q + 3]);
        g_xw[(size_t)i * 4 + q] = v;
        g_h [(size_t)i * 4 + q] = make_float4(sl * v.x, sl * v.y, sl * v.z, sl * v.w);
    }
}

// Layer-1 edge scatter: h[dst] += isd[s]*isd[d] * xw[src]  (4x red.v4.f32)
__global__ void k_edge1(const int* __restrict__ src,
                        const int* __restrict__ dst, int E) {
    int e = blockIdx.x * blockDim.x + threadIdx.x;
    if (e >= E) return;
    int s = src[e];
    int d = dst[e];
    float nrm = g_isd[s] * g_isd[d];
    const float4* xs = &g_xw[(size_t)s * 4];
    float4*       hd = &g_h [(size_t)d * 4];
#pragma unroll
    for (int q = 0; q < 4; q++) {
        float4 v = xs[q];
        asm volatile(
            "red.global.add.v4.f32 [%0], {%1, %2, %3, %4};"
            :: "l"(hd + q),
               "f"(nrm * v.x), "f"(nrm * v.y), "f"(nrm * v.z), "f"(nrm * v.w)
            : "memory");
    }
}

// Per-node epilogue of layer 1 + start of layer 2:
//   h = relu(h + b1); g = h @ W2; out = b2 + isd^2 * g   (self-loop of layer 2)
__global__ void k_node2(const float* __restrict__ b1,
                        const float* __restrict__ W2,
                        const float* __restrict__ b2,
                        float* __restrict__ out, int n) {
    int i = blockIdx.x * blockDim.x + threadIdx.x;
    if (i >= n) return;
    float acc = 0.f;
#pragma unroll
    for (int q = 0; q < 4; q++) {
        float4 h = g_h[(size_t)i * 4 + q];
        float h0 = fmaxf(h.x + __ldg(&b1[4 * q + 0]), 0.f);
        float h1 = fmaxf(h.y + __ldg(&b1[4 * q + 1]), 0.f);
        float h2 = fmaxf(h.z + __ldg(&b1[4 * q + 2]), 0.f);
        float h3 = fmaxf(h.w + __ldg(&b1[4 * q + 3]), 0.f);
        acc += h0 * __ldg(&W2[4 * q + 0]) + h1 * __ldg(&W2[4 * q + 1])
             + h2 * __ldg(&W2[4 * q + 2]) + h3 * __ldg(&W2[4 * q + 3]);
    }
    g_g[i] = acc;
    float isd = g_isd[i];
    out[i] = __ldg(&b2[0]) + isd * isd * acc;   // fully overwrites poisoned out
}

// Layer-2 edge scatter: out[dst] += isd[s]*isd[d] * g[src]
__global__ void k_edge2(const int* __restrict__ src,
                        const int* __restrict__ dst,
                        float* __restrict__ out, int E) {
    int e = blockIdx.x * blockDim.x + threadIdx.x;
    if (e >= E) return;
    int s = src[e];
    int d = dst[e];
    float v = g_isd[s] * g_isd[d] * g_g[s];
    atomicAdd(&out[d], v);   // compiles to RED (result unused)
}

// ---------------------------------------------------------------------------
extern "C" void kernel_launch(void* const* d_in, const int* in_sizes, int n_in,
                              void* d_out, int out_size) {
    const float* x  = (const float*)d_in[0];
    const int*   ei = (const int*)  d_in[1];
    const float* W1 = (const float*)d_in[2];
    const float* b1 = (const float*)d_in[3];
    const float* W2 = (const float*)d_in[4];
    const float* b2 = (const float*)d_in[5];
    float* out = (float*)d_out;

    int n = in_sizes[0] / 3;
    int E = in_sizes[1] / 2;
    const int* src = ei;
    const int* dst = ei + E;

    const int T = 256;
    int nb_n = (n + T - 1) / T;
    int nb_e = (E + T - 1) / T;

    k_zero_deg<<<nb_n, T>>>(n);
    k_count   <<<nb_e, T>>>(dst, E);
    k_node1   <<<nb_n, T>>>(x, W1, n);
    k_edge1   <<<nb_e, T>>>(src, dst, E);
    k_node2   <<<nb_n, T>>>(b1, W2, b2, out, n);
    k_edge2   <<<nb_e, T>>>(src, dst, out, E);
}

// round 2
// speedup vs baseline: 2.1963x; 2.1963x over previous
#include <cuda_runtime.h>
#include <stdint.h>

// TrafficGCN: 2-layer GCN, N=100000, E=3200000, HIDDEN=16.
// Key optimization: GCN aggregation is LINEAR, so aggregate the raw 3-dim
// input features (one float4) instead of 16-dim transformed features, and
// apply W1 after aggregation. isd[s] is pre-folded into the message; isd[d]
// is applied in a post-pass. Edge kernels carry minimal payload.
//
// Inputs (metadata order):
//   d_in[0] = x  f32 [N,3], d_in[1] = edge_index i32 [2,E],
//   d_in[2] = W1 f32 [3,16], d_in[3] = b1 f32 [16],
//   d_in[4] = W2 f32 [16,1], d_in[5] = b2 f32 [1]
// Output: f32 [N]

#define MAXN 100608
#define HID 16

__device__ int    g_degcnt[MAXN];
__device__ float  g_isd[MAXN];
__device__ float4 g_px[MAXN];    // isd[i] * x[i], w=0  (layer-1 message)
__device__ float4 g_aggx[MAXN];  // seeded with px[i]; edges add px[s]
__device__ float  g_p[MAXN];     // isd[i] * g[i]       (layer-2 message)

// ---------------------------------------------------------------------------
__global__ void k_zero_deg(int n) {
    int i = blockIdx.x * blockDim.x + threadIdx.x;
    if (i < n) g_degcnt[i] = 0;
}

__global__ void k_count(const int* __restrict__ dst, int E) {
    int e = blockIdx.x * blockDim.x + threadIdx.x;
    if (e < E) atomicAdd(&g_degcnt[dst[e]], 1);
}

// Per-node: isd = rsqrt(deg+1); px = isd*x (w=0); aggx seeded with px (self-loop)
__global__ void k_node1(const float* __restrict__ x, int n) {
    int i = blockIdx.x * blockDim.x + threadIdx.x;
    if (i >= n) return;
    float isd = rsqrtf((float)(g_degcnt[i] + 1));
    g_isd[i] = isd;
    float4 p = make_float4(isd * x[3*i+0], isd * x[3*i+1], isd * x[3*i+2], 0.f);
    g_px[i]   = p;
    g_aggx[i] = p;   // self-loop seed: final feat = isd[d] * aggx[d]
}

// Layer-1 edge scatter: aggx[dst] += px[src]   (single red.v4.f32 per edge)
__global__ void k_edge1(const int* __restrict__ src,
                        const int* __restrict__ dst, int E) {
    int e = blockIdx.x * blockDim.x + threadIdx.x;
    if (e >= E) return;
    int s = src[e];
    int d = dst[e];
    float4 v = g_px[s];
    asm volatile(
        "red.global.add.v4.f32 [%0], {%1, %2, %3, %4};"
        :: "l"(&g_aggx[d]), "f"(v.x), "f"(v.y), "f"(v.z), "f"(v.w)
        : "memory");
}

// Per-node: feat = isd*aggx; h = relu(feat@W1 + b1); g = h@W2;
// p = isd*g; seed out accumulator with p (layer-2 self-loop).
__global__ void k_node2(const float* __restrict__ W1,
                        const float* __restrict__ b1,
                        const float* __restrict__ W2,
                        float* __restrict__ out, int n) {
    int i = blockIdx.x * blockDim.x + threadIdx.x;
    if (i >= n) return;
    float isd = g_isd[i];
    float4 a = g_aggx[i];
    float f0 = isd * a.x, f1 = isd * a.y, f2 = isd * a.z;

    float acc = 0.f;
#pragma unroll
    for (int c = 0; c < HID; c++) {
        float h = f0 * __ldg(&W1[c]) + f1 * __ldg(&W1[HID + c])
                + f2 * __ldg(&W1[2 * HID + c]) + __ldg(&b1[c]);
        acc += fmaxf(h, 0.f) * __ldg(&W2[c]);
    }
    float p = isd * acc;
    g_p[i]  = p;
    out[i]  = p;   // accumulator seed (overwrites poison)
}

// Layer-2 edge scatter: out[dst] += p[src]
__global__ void k_edge2(const int* __restrict__ src,
                        const int* __restrict__ dst,
                        float* __restrict__ out, int E) {
    int e = blockIdx.x * blockDim.x + threadIdx.x;
    if (e >= E) return;
    atomicAdd(&out[dst[e]], g_p[src[e]]);   // RED (result unused)
}

// Final: out = b2 + isd * accum
__global__ void k_node3(const float* __restrict__ b2,
                        float* __restrict__ out, int n) {
    int i = blockIdx.x * blockDim.x + threadIdx.x;
    if (i < n) out[i] = __ldg(&b2[0]) + g_isd[i] * out[i];
}

// ---------------------------------------------------------------------------
extern "C" void kernel_launch(void* const* d_in, const int* in_sizes, int n_in,
                              void* d_out, int out_size) {
    const float* x  = (const float*)d_in[0];
    const int*   ei = (const int*)  d_in[1];
    const float* W1 = (const float*)d_in[2];
    const float* b1 = (const float*)d_in[3];
    const float* W2 = (const float*)d_in[4];
    const float* b2 = (const float*)d_in[5];
    float* out = (float*)d_out;

    int n = in_sizes[0] / 3;
    int E = in_sizes[1] / 2;
    const int* src = ei;
    const int* dst = ei + E;

    const int T = 256;
    int nb_n = (n + T - 1) / T;
    int nb_e = (E + T - 1) / T;

    k_zero_deg<<<nb_n, T>>>(n);
    k_count   <<<nb_e, T>>>(dst, E);
    k_node1   <<<nb_n, T>>>(x, n);
    k_edge1   <<<nb_e, T>>>(src, dst, E);
    k_node2   <<<nb_n, T>>>(W1, b1, W2, out, n);
    k_edge2   <<<nb_e, T>>>(src, dst, out, E);
    k_node3   <<<nb_n, T>>>(b2, out, n);
}